// round 10
// baseline (speedup 1.0000x reference)
#include <cuda_runtime.h>
#include <cuda_bf16.h>
#include <cstdint>

#define NN 50000
#define EE 800000
#define FF 128
#define CC 64
#define CAP 64          // bucket capacity per row (Poisson(16) tail: P(deg>=64) ~ 1e-19)
#define NT ((NN + 127) / 128)   // 391 row tiles
#define GGRID 148

// ---------------- scratch (static device globals; no allocation) ----------------
__device__ int   g_fill[NN];
__device__ int2  g_edge[(size_t)NN * CAP];     // (src, val-bits) bucketed by dst row
__device__ __nv_bfloat16 g_sh[(size_t)NN * FF];  // spmm1 output, hi part
__device__ __nv_bfloat16 g_sl[(size_t)NN * FF];  // spmm1 output, lo part
__device__ __nv_bfloat16 g_w1h[FF * FF], g_w1l[FF * FF];
__device__ __nv_bfloat16 g_w2h[CC * FF], g_w2l[CC * FF];
__device__ float g_p[(size_t)NN * CC];         // relu(s@W1^T)@W2^T pre-aggregation logits

// ---------------- bucket CSR build ----------------
__global__ void k_zero() {
    int i = blockIdx.x * blockDim.x + threadIdx.x;
    if (i < NN) g_fill[i] = 0;
}

__global__ void k_scatter(const int* __restrict__ src, const int* __restrict__ dst,
                          const float* __restrict__ vals) {
    int e = blockIdx.x * blockDim.x + threadIdx.x;
    if (e < EE) {
        int d = dst[e];
        int p = atomicAdd(&g_fill[d], 1);
        if (p < CAP)
            g_edge[(size_t)d * CAP + p] = make_int2(src[e], __float_as_int(vals[e]));
    }
}

// ---------------- weight pre-split (once per launch) ----------------
__global__ void k_wsplit(const float* __restrict__ W1, const float* __restrict__ W2) {
    int i = blockIdx.x * blockDim.x + threadIdx.x;
    if (i < FF * FF) {
        float v = W1[i];
        __nv_bfloat16 h = __float2bfloat16(v);
        g_w1h[i] = h;
        g_w1l[i] = __float2bfloat16(v - __bfloat162float(h));
    }
    if (i < CC * FF) {
        float v = W2[i];
        __nv_bfloat16 h = __float2bfloat16(v);
        g_w2h[i] = h;
        g_w2l[i] = __float2bfloat16(v - __bfloat162float(h));
    }
}

// ---------------- SpMM width 128: 2 warps per row (edge split), 4 rows/block ----------------
__global__ void k_spmm128(const float* __restrict__ X) {
    __shared__ float4 part[4][32];
    int tid = threadIdx.x;
    int w = tid >> 5, lane = tid & 31;
    int rloc = w >> 1, half = w & 1;
    int row = blockIdx.x * 4 + rloc;

    float4 acc = make_float4(0.f, 0.f, 0.f, 0.f);
    if (row < NN) {
        int n = min(g_fill[row], CAP);
        int nh = (n + 1) >> 1;
        int beg = half ? nh : 0;
        int end = half ? n : nh;
        const int2* eb = g_edge + (size_t)row * CAP;
        for (int e = beg; e < end; e += 32) {
            int m = min(32, end - e);
            int2 ed = (lane < m) ? eb[e + lane] : make_int2(0, 0);
            #pragma unroll 4
            for (int k = 0; k < m; k++) {
                int   sk = __shfl_sync(0xffffffffu, ed.x, k);
                float vk = __int_as_float(__shfl_sync(0xffffffffu, ed.y, k));
                float4 xv = *(const float4*)(X + (size_t)sk * FF + lane * 4);
                acc.x += vk * xv.x; acc.y += vk * xv.y;
                acc.z += vk * xv.z; acc.w += vk * xv.w;
            }
        }
    }
    if (half) part[rloc][lane] = acc;
    __syncthreads();
    if (!half && row < NN) {
        float4 o = part[rloc][lane];
        float v[4] = {acc.x + o.x, acc.y + o.y, acc.z + o.z, acc.w + o.w};
        __nv_bfloat16 hh[4], ll[4];
        #pragma unroll
        for (int q = 0; q < 4; q++) {
            hh[q] = __float2bfloat16(v[q]);
            ll[q] = __float2bfloat16(v[q] - __bfloat162float(hh[q]));
        }
        size_t base = (size_t)row * FF + lane * 4;
        *(uint2*)(g_sh + base) = *(uint2*)hh;
        *(uint2*)(g_sl + base) = *(uint2*)ll;
    }
}

// ---------------- persistent tensor-core fused GEMM ----------------
// p = relu(S @ W1^T) @ W2^T; mma m16n8k16 bf16 hi/lo split (3 MMAs).
// grid=148 persistent; weights staged in smem once per block.

#define LDB 136

__device__ __forceinline__ uint32_t smem_u32(const void* p) {
    return (uint32_t)__cvta_generic_to_shared(p);
}

#define LDSM4(r0, r1, r2, r3, addr)                                           \
    asm volatile("ldmatrix.sync.aligned.m8n8.x4.shared.b16 {%0,%1,%2,%3},[%4];" \
                 : "=r"(r0), "=r"(r1), "=r"(r2), "=r"(r3) : "r"(addr))

#define MMA16816(d, a0, a1, a2, a3, b0, b1)                                   \
    asm volatile("mma.sync.aligned.m16n8k16.row.col.f32.bf16.bf16.f32 "        \
                 "{%0,%1,%2,%3},{%4,%5,%6,%7},{%8,%9},{%0,%1,%2,%3};"          \
                 : "+f"(d[0]), "+f"(d[1]), "+f"(d[2]), "+f"(d[3])              \
                 : "r"(a0), "r"(a1), "r"(a2), "r"(a3), "r"(b0), "r"(b1))

__device__ __forceinline__ void split_store(__nv_bfloat16* Hp, __nv_bfloat16* Lp,
                                            int off, float v) {
    __nv_bfloat16 h = __float2bfloat16(v);
    Hp[off] = h;
    Lp[off] = __float2bfloat16(v - __bfloat162float(h));
}

__global__ void __launch_bounds__(512, 1)
k_gemm_fused() {
    extern __shared__ __nv_bfloat16 smb[];
    __nv_bfloat16* Sh  = smb;                     // 128*136
    __nv_bfloat16* Sl  = Sh  + 128 * LDB;
    __nv_bfloat16* W1h = Sl  + 128 * LDB;
    __nv_bfloat16* W1l = W1h + 128 * LDB;
    __nv_bfloat16* W2h = W1l + 128 * LDB;         // 64*136
    __nv_bfloat16* W2l = W2h + 64 * LDB;

    int tid = threadIdx.x;
    int lane = tid & 31, w = tid >> 5;

    for (int idx = tid; idx < 128 * 16; idx += 512) {
        int r = idx >> 4, c8 = idx & 15;
        *(uint4*)(&W1h[r * LDB + c8 * 8]) = ((const uint4*)(g_w1h + r * FF))[c8];
        *(uint4*)(&W1l[r * LDB + c8 * 8]) = ((const uint4*)(g_w1l + r * FF))[c8];
    }
    for (int idx = tid; idx < 64 * 16; idx += 512) {
        int r = idx >> 4, c8 = idx & 15;
        *(uint4*)(&W2h[r * LDB + c8 * 8]) = ((const uint4*)(g_w2h + r * FF))[c8];
        *(uint4*)(&W2l[r * LDB + c8 * 8]) = ((const uint4*)(g_w2l + r * FF))[c8];
    }

    int wm = w & 7;
    int wn = w >> 3;
    int arow = (lane & 15), acol8 = (lane >> 4) << 3;
    int r_lo = lane >> 2, cpair = (lane & 3) * 2;
    const uint4 zero4 = make_uint4(0, 0, 0, 0);

    for (int t = blockIdx.x; t < NT; t += GGRID) {
        int row0 = t * 128;
        __syncthreads();

        for (int idx = tid; idx < 128 * 16; idx += 512) {
            int r = idx >> 4, c8 = idx & 15;
            int gr = row0 + r;
            uint4 vh = zero4, vl = zero4;
            if (gr < NN) {
                vh = ((const uint4*)(g_sh + (size_t)gr * FF))[c8];
                vl = ((const uint4*)(g_sl + (size_t)gr * FF))[c8];
            }
            *(uint4*)(&Sh[r * LDB + c8 * 8]) = vh;
            *(uint4*)(&Sl[r * LDB + c8 * 8]) = vl;
        }
        __syncthreads();

        // ---- phase A: h = relu(S @ W1^T) ----
        float acc[8][4];
        #pragma unroll
        for (int j = 0; j < 8; j++)
            #pragma unroll
            for (int q = 0; q < 4; q++) acc[j][q] = 0.f;

        #pragma unroll
        for (int ks = 0; ks < 8; ks++) {
            int k0 = ks * 16;
            uint32_t ah[4], al[4];
            LDSM4(ah[0], ah[1], ah[2], ah[3],
                  smem_u32(&Sh[(wm * 16 + arow) * LDB + k0 + acol8]));
            LDSM4(al[0], al[1], al[2], al[3],
                  smem_u32(&Sl[(wm * 16 + arow) * LDB + k0 + acol8]));
            uint32_t bh0[8], bh1[8], bl0[8], bl1[8];
            #pragma unroll
            for (int jj = 0; jj < 4; jj++) {
                int nrow = wn * 64 + jj * 16 + arow;
                uint32_t p0, p1, p2, p3;
                LDSM4(p0, p1, p2, p3, smem_u32(&W1h[nrow * LDB + k0 + acol8]));
                bh0[2 * jj] = p0; bh1[2 * jj] = p2;
                bh0[2 * jj + 1] = p1; bh1[2 * jj + 1] = p3;
                LDSM4(p0, p1, p2, p3, smem_u32(&W1l[nrow * LDB + k0 + acol8]));
                bl0[2 * jj] = p0; bl1[2 * jj] = p2;
                bl0[2 * jj + 1] = p1; bl1[2 * jj + 1] = p3;
            }
            #pragma unroll
            for (int j = 0; j < 8; j++) {
                MMA16816(acc[j], ah[0], ah[1], ah[2], ah[3], bh0[j], bh1[j]);
                MMA16816(acc[j], ah[0], ah[1], ah[2], ah[3], bl0[j], bl1[j]);
                MMA16816(acc[j], al[0], al[1], al[2], al[3], bh0[j], bh1[j]);
            }
        }
        __syncthreads();

        #pragma unroll
        for (int j = 0; j < 8; j++) {
            int col = wn * 64 + j * 8 + cpair;
            int r1 = wm * 16 + r_lo, r2 = r1 + 8;
            split_store(Sh, Sl, r1 * LDB + col,     fmaxf(acc[j][0], 0.f));
            split_store(Sh, Sl, r1 * LDB + col + 1, fmaxf(acc[j][1], 0.f));
            split_store(Sh, Sl, r2 * LDB + col,     fmaxf(acc[j][2], 0.f));
            split_store(Sh, Sl, r2 * LDB + col + 1, fmaxf(acc[j][3], 0.f));
        }
        __syncthreads();

        // ---- phase B: p = h @ W2^T ----
        float ac2[4][4];
        #pragma unroll
        for (int j = 0; j < 4; j++)
            #pragma unroll
            for (int q = 0; q < 4; q++) ac2[j][q] = 0.f;

        #pragma unroll
        for (int ks = 0; ks < 8; ks++) {
            int k0 = ks * 16;
            uint32_t ah[4], al[4];
            LDSM4(ah[0], ah[1], ah[2], ah[3],
                  smem_u32(&Sh[(wm * 16 + arow) * LDB + k0 + acol8]));
            LDSM4(al[0], al[1], al[2], al[3],
                  smem_u32(&Sl[(wm * 16 + arow) * LDB + k0 + acol8]));
            uint32_t bh0[4], bh1[4], bl0[4], bl1[4];
            #pragma unroll
            for (int jj = 0; jj < 2; jj++) {
                int nrow = wn * 32 + jj * 16 + arow;
                uint32_t p0, p1, p2, p3;
                LDSM4(p0, p1, p2, p3, smem_u32(&W2h[nrow * LDB + k0 + acol8]));
                bh0[2 * jj] = p0; bh1[2 * jj] = p2;
                bh0[2 * jj + 1] = p1; bh1[2 * jj + 1] = p3;
                LDSM4(p0, p1, p2, p3, smem_u32(&W2l[nrow * LDB + k0 + acol8]));
                bl0[2 * jj] = p0; bl1[2 * jj] = p2;
                bl0[2 * jj + 1] = p1; bl1[2 * jj + 1] = p3;
            }
            #pragma unroll
            for (int j = 0; j < 4; j++) {
                MMA16816(ac2[j], ah[0], ah[1], ah[2], ah[3], bh0[j], bh1[j]);
                MMA16816(ac2[j], ah[0], ah[1], ah[2], ah[3], bl0[j], bl1[j]);
                MMA16816(ac2[j], al[0], al[1], al[2], al[3], bh0[j], bh1[j]);
            }
        }

        #pragma unroll
        for (int j = 0; j < 4; j++) {
            int col = wn * 32 + j * 8 + cpair;
            int gr1 = row0 + wm * 16 + r_lo, gr2 = gr1 + 8;
            if (gr1 < NN)
                *(float2*)(g_p + (size_t)gr1 * CC + col) = make_float2(ac2[j][0], ac2[j][1]);
            if (gr2 < NN)
                *(float2*)(g_p + (size_t)gr2 * CC + col) = make_float2(ac2[j][2], ac2[j][3]);
        }
    }
}

// ---------------- SpMM width 64 + softmax: 2 warps per row, 4 rows/block ----------------
__global__ void k_spmm64_softmax(float* __restrict__ out) {
    __shared__ float2 part[4][32];
    int tid = threadIdx.x;
    int w = tid >> 5, lane = tid & 31;
    int rloc = w >> 1, half = w & 1;
    int row = blockIdx.x * 4 + rloc;

    float2 acc = make_float2(0.f, 0.f);
    if (row < NN) {
        int n = min(g_fill[row], CAP);
        int nh = (n + 1) >> 1;
        int beg = half ? nh : 0;
        int end = half ? n : nh;
        const int2* eb = g_edge + (size_t)row * CAP;
        for (int e = beg; e < end; e += 32) {
            int m = min(32, end - e);
            int2 ed = (lane < m) ? eb[e + lane] : make_int2(0, 0);
            #pragma unroll 4
            for (int k = 0; k < m; k++) {
                int   sk = __shfl_sync(0xffffffffu, ed.x, k);
                float vk = __int_as_float(__shfl_sync(0xffffffffu, ed.y, k));
                float2 xv = *(const float2*)(g_p + (size_t)sk * CC + lane * 2);
                acc.x += vk * xv.x; acc.y += vk * xv.y;
            }
        }
    }
    if (half) part[rloc][lane] = acc;
    __syncthreads();
    if (!half && row < NN) {
        float2 o = part[rloc][lane];
        acc.x += o.x; acc.y += o.y;
        float m2 = fmaxf(acc.x, acc.y);
        #pragma unroll
        for (int off = 16; off > 0; off >>= 1)
            m2 = fmaxf(m2, __shfl_xor_sync(0xffffffffu, m2, off));
        float ea = __expf(acc.x - m2), eb2 = __expf(acc.y - m2);
        float s = ea + eb2;
        #pragma unroll
        for (int off = 16; off > 0; off >>= 1)
            s += __shfl_xor_sync(0xffffffffu, s, off);
        float inv = 1.f / s;
        *(float2*)(out + (size_t)row * CC + lane * 2) = make_float2(ea * inv, eb2 * inv);
    }
}

// ---------------- launch ----------------
extern "C" void kernel_launch(void* const* d_in, const int* in_sizes, int n_in,
                              void* d_out, int out_size) {
    const float* x    = (const float*)d_in[0];
    const float* vals = (const float*)d_in[1];
    const float* W1   = (const float*)d_in[2];
    const float* W2   = (const float*)d_in[3];
    const int*   src  = (const int*)d_in[4];
    const int*   dst  = (const int*)d_in[5];
    float* out = (float*)d_out;

    const int smemF = (4 * 128 * LDB + 2 * 64 * LDB) * 2;   // 174,080 B
    static bool attr_done = false;
    if (!attr_done) {
        cudaFuncSetAttribute(k_gemm_fused, cudaFuncAttributeMaxDynamicSharedMemorySize, smemF);
        attr_done = true;
    }

    // bucket CSR by dst + weight split
    k_zero<<<(NN + 255) / 256, 256>>>();
    k_scatter<<<(EE + 255) / 256, 256>>>(src, dst, vals);
    k_wsplit<<<(FF * FF + 255) / 256, 256>>>(W1, W2);

    // layer 1 aggregation (2 warps/row, writes bf16 hi/lo)
    k_spmm128<<<(NN + 3) / 4, 256>>>(x);
    // dense parts of both layers on tensor cores, persistent grid
    k_gemm_fused<<<GGRID, 512, smemF>>>();
    // layer 2 aggregation + softmax (2 warps/row)
    k_spmm64_softmax<<<(NN + 3) / 4, 256>>>(out);
}

// round 11
// speedup vs baseline: 1.0150x; 1.0150x over previous
#include <cuda_runtime.h>
#include <cuda_bf16.h>
#include <cstdint>

#define NN 50000
#define EE 800000
#define FF 128
#define CC 64
#define CAP 64          // bucket capacity per row (Poisson(16) tail: P(deg>=64) ~ 1e-19)
#define NT ((NN + 127) / 128)   // 391 row tiles
#define GGRID 148

// ---------------- scratch (static device globals; no allocation) ----------------
__device__ int   g_fill[NN];
__device__ int2  g_edge[(size_t)NN * CAP];     // (src, val-bits) bucketed by dst row
__device__ __nv_bfloat16 g_sh[(size_t)NN * FF];  // spmm1 output, hi part
__device__ __nv_bfloat16 g_sl[(size_t)NN * FF];  // spmm1 output, lo part
__device__ __nv_bfloat16 g_w1h[FF * FF], g_w1l[FF * FF];
__device__ __nv_bfloat16 g_w2h[CC * FF], g_w2l[CC * FF];
__device__ float g_p[(size_t)NN * CC];         // relu(s@W1^T)@W2^T pre-aggregation logits

// ---------------- bucket CSR build ----------------
__global__ void k_zero() {
    int i = blockIdx.x * blockDim.x + threadIdx.x;
    if (i < NN) g_fill[i] = 0;
}

__global__ void k_scatter(const int* __restrict__ src, const int* __restrict__ dst,
                          const float* __restrict__ vals) {
    int e = blockIdx.x * blockDim.x + threadIdx.x;
    if (e < EE) {
        int d = dst[e];
        int p = atomicAdd(&g_fill[d], 1);
        if (p < CAP)
            g_edge[(size_t)d * CAP + p] = make_int2(src[e], __float_as_int(vals[e]));
    }
}

// ---------------- weight pre-split (once per launch) ----------------
__global__ void k_wsplit(const float* __restrict__ W1, const float* __restrict__ W2) {
    int i = blockIdx.x * blockDim.x + threadIdx.x;
    if (i < FF * FF) {
        float v = W1[i];
        __nv_bfloat16 h = __float2bfloat16(v);
        g_w1h[i] = h;
        g_w1l[i] = __float2bfloat16(v - __bfloat162float(h));
    }
    if (i < CC * FF) {
        float v = W2[i];
        __nv_bfloat16 h = __float2bfloat16(v);
        g_w2h[i] = h;
        g_w2l[i] = __float2bfloat16(v - __bfloat162float(h));
    }
}

// ---------------- SpMM width 128: one warp per row, MLP-8 batched gather ----------------
__global__ void k_spmm128(const float* __restrict__ X) {
    int row = (blockIdx.x * blockDim.x + threadIdx.x) >> 5;
    int lane = threadIdx.x & 31;
    if (row >= NN) return;
    int n = min(g_fill[row], CAP);
    const int2* eb = g_edge + (size_t)row * CAP;
    float4 acc0 = make_float4(0.f, 0.f, 0.f, 0.f);
    float4 acc1 = make_float4(0.f, 0.f, 0.f, 0.f);
    for (int e = 0; e < n; e += 32) {
        int m = min(32, n - e);
        int2 ed = (lane < m) ? eb[e + lane] : make_int2(0, 0);
        int kk = 0;
        for (; kk + 8 <= m; kk += 8) {
            float4 xv[8];
            float  vk[8];
            #pragma unroll
            for (int q = 0; q < 8; q++) {
                int   sk = __shfl_sync(0xffffffffu, ed.x, kk + q);
                vk[q]    = __int_as_float(__shfl_sync(0xffffffffu, ed.y, kk + q));
                xv[q]    = *(const float4*)(X + (size_t)sk * FF + lane * 4);
            }
            #pragma unroll
            for (int q = 0; q < 8; q += 2) {
                acc0.x += vk[q] * xv[q].x;     acc0.y += vk[q] * xv[q].y;
                acc0.z += vk[q] * xv[q].z;     acc0.w += vk[q] * xv[q].w;
                acc1.x += vk[q+1] * xv[q+1].x; acc1.y += vk[q+1] * xv[q+1].y;
                acc1.z += vk[q+1] * xv[q+1].z; acc1.w += vk[q+1] * xv[q+1].w;
            }
        }
        for (; kk < m; kk++) {
            int   sk = __shfl_sync(0xffffffffu, ed.x, kk);
            float vk = __int_as_float(__shfl_sync(0xffffffffu, ed.y, kk));
            float4 xv = *(const float4*)(X + (size_t)sk * FF + lane * 4);
            acc0.x += vk * xv.x; acc0.y += vk * xv.y;
            acc0.z += vk * xv.z; acc0.w += vk * xv.w;
        }
    }
    float v[4] = {acc0.x + acc1.x, acc0.y + acc1.y, acc0.z + acc1.z, acc0.w + acc1.w};
    __nv_bfloat16 hh[4], ll[4];
    #pragma unroll
    for (int q = 0; q < 4; q++) {
        hh[q] = __float2bfloat16(v[q]);
        ll[q] = __float2bfloat16(v[q] - __bfloat162float(hh[q]));
    }
    size_t base = (size_t)row * FF + lane * 4;
    *(uint2*)(g_sh + base) = *(uint2*)hh;
    *(uint2*)(g_sl + base) = *(uint2*)ll;
}

// ---------------- persistent tensor-core fused GEMM ----------------
// p = relu(S @ W1^T) @ W2^T; mma m16n8k16 bf16 hi/lo split (3 MMAs).

#define LDB 136

__device__ __forceinline__ uint32_t smem_u32(const void* p) {
    return (uint32_t)__cvta_generic_to_shared(p);
}

#define LDSM4(r0, r1, r2, r3, addr)                                           \
    asm volatile("ldmatrix.sync.aligned.m8n8.x4.shared.b16 {%0,%1,%2,%3},[%4];" \
                 : "=r"(r0), "=r"(r1), "=r"(r2), "=r"(r3) : "r"(addr))

#define MMA16816(d, a0, a1, a2, a3, b0, b1)                                   \
    asm volatile("mma.sync.aligned.m16n8k16.row.col.f32.bf16.bf16.f32 "        \
                 "{%0,%1,%2,%3},{%4,%5,%6,%7},{%8,%9},{%0,%1,%2,%3};"          \
                 : "+f"(d[0]), "+f"(d[1]), "+f"(d[2]), "+f"(d[3])              \
                 : "r"(a0), "r"(a1), "r"(a2), "r"(a3), "r"(b0), "r"(b1))

__device__ __forceinline__ void split_store(__nv_bfloat16* Hp, __nv_bfloat16* Lp,
                                            int off, float v) {
    __nv_bfloat16 h = __float2bfloat16(v);
    Hp[off] = h;
    Lp[off] = __float2bfloat16(v - __bfloat162float(h));
}

__global__ void __launch_bounds__(512, 1)
k_gemm_fused() {
    extern __shared__ __nv_bfloat16 smb[];
    __nv_bfloat16* Sh  = smb;                     // 128*136
    __nv_bfloat16* Sl  = Sh  + 128 * LDB;
    __nv_bfloat16* W1h = Sl  + 128 * LDB;
    __nv_bfloat16* W1l = W1h + 128 * LDB;
    __nv_bfloat16* W2h = W1l + 128 * LDB;         // 64*136
    __nv_bfloat16* W2l = W2h + 64 * LDB;

    int tid = threadIdx.x;
    int lane = tid & 31, w = tid >> 5;

    for (int idx = tid; idx < 128 * 16; idx += 512) {
        int r = idx >> 4, c8 = idx & 15;
        *(uint4*)(&W1h[r * LDB + c8 * 8]) = ((const uint4*)(g_w1h + r * FF))[c8];
        *(uint4*)(&W1l[r * LDB + c8 * 8]) = ((const uint4*)(g_w1l + r * FF))[c8];
    }
    for (int idx = tid; idx < 64 * 16; idx += 512) {
        int r = idx >> 4, c8 = idx & 15;
        *(uint4*)(&W2h[r * LDB + c8 * 8]) = ((const uint4*)(g_w2h + r * FF))[c8];
        *(uint4*)(&W2l[r * LDB + c8 * 8]) = ((const uint4*)(g_w2l + r * FF))[c8];
    }

    int wm = w & 7;
    int wn = w >> 3;
    int arow = (lane & 15), acol8 = (lane >> 4) << 3;
    int r_lo = lane >> 2, cpair = (lane & 3) * 2;
    const uint4 zero4 = make_uint4(0, 0, 0, 0);

    for (int t = blockIdx.x; t < NT; t += GGRID) {
        int row0 = t * 128;
        __syncthreads();

        for (int idx = tid; idx < 128 * 16; idx += 512) {
            int r = idx >> 4, c8 = idx & 15;
            int gr = row0 + r;
            uint4 vh = zero4, vl = zero4;
            if (gr < NN) {
                vh = ((const uint4*)(g_sh + (size_t)gr * FF))[c8];
                vl = ((const uint4*)(g_sl + (size_t)gr * FF))[c8];
            }
            *(uint4*)(&Sh[r * LDB + c8 * 8]) = vh;
            *(uint4*)(&Sl[r * LDB + c8 * 8]) = vl;
        }
        __syncthreads();

        // ---- phase A: h = relu(S @ W1^T) ----
        float acc[8][4];
        #pragma unroll
        for (int j = 0; j < 8; j++)
            #pragma unroll
            for (int q = 0; q < 4; q++) acc[j][q] = 0.f;

        #pragma unroll
        for (int ks = 0; ks < 8; ks++) {
            int k0 = ks * 16;
            uint32_t ah[4], al[4];
            LDSM4(ah[0], ah[1], ah[2], ah[3],
                  smem_u32(&Sh[(wm * 16 + arow) * LDB + k0 + acol8]));
            LDSM4(al[0], al[1], al[2], al[3],
                  smem_u32(&Sl[(wm * 16 + arow) * LDB + k0 + acol8]));
            uint32_t bh0[8], bh1[8], bl0[8], bl1[8];
            #pragma unroll
            for (int jj = 0; jj < 4; jj++) {
                int nrow = wn * 64 + jj * 16 + arow;
                uint32_t p0, p1, p2, p3;
                LDSM4(p0, p1, p2, p3, smem_u32(&W1h[nrow * LDB + k0 + acol8]));
                bh0[2 * jj] = p0; bh1[2 * jj] = p2;
                bh0[2 * jj + 1] = p1; bh1[2 * jj + 1] = p3;
                LDSM4(p0, p1, p2, p3, smem_u32(&W1l[nrow * LDB + k0 + acol8]));
                bl0[2 * jj] = p0; bl1[2 * jj] = p2;
                bl0[2 * jj + 1] = p1; bl1[2 * jj + 1] = p3;
            }
            #pragma unroll
            for (int j = 0; j < 8; j++) {
                MMA16816(acc[j], ah[0], ah[1], ah[2], ah[3], bh0[j], bh1[j]);
                MMA16816(acc[j], ah[0], ah[1], ah[2], ah[3], bl0[j], bl1[j]);
                MMA16816(acc[j], al[0], al[1], al[2], al[3], bh0[j], bh1[j]);
            }
        }
        __syncthreads();

        #pragma unroll
        for (int j = 0; j < 8; j++) {
            int col = wn * 64 + j * 8 + cpair;
            int r1 = wm * 16 + r_lo, r2 = r1 + 8;
            split_store(Sh, Sl, r1 * LDB + col,     fmaxf(acc[j][0], 0.f));
            split_store(Sh, Sl, r1 * LDB + col + 1, fmaxf(acc[j][1], 0.f));
            split_store(Sh, Sl, r2 * LDB + col,     fmaxf(acc[j][2], 0.f));
            split_store(Sh, Sl, r2 * LDB + col + 1, fmaxf(acc[j][3], 0.f));
        }
        __syncthreads();

        // ---- phase B: p = h @ W2^T ----
        float ac2[4][4];
        #pragma unroll
        for (int j = 0; j < 4; j++)
            #pragma unroll
            for (int q = 0; q < 4; q++) ac2[j][q] = 0.f;

        #pragma unroll
        for (int ks = 0; ks < 8; ks++) {
            int k0 = ks * 16;
            uint32_t ah[4], al[4];
            LDSM4(ah[0], ah[1], ah[2], ah[3],
                  smem_u32(&Sh[(wm * 16 + arow) * LDB + k0 + acol8]));
            LDSM4(al[0], al[1], al[2], al[3],
                  smem_u32(&Sl[(wm * 16 + arow) * LDB + k0 + acol8]));
            uint32_t bh0[4], bh1[4], bl0[4], bl1[4];
            #pragma unroll
            for (int jj = 0; jj < 2; jj++) {
                int nrow = wn * 32 + jj * 16 + arow;
                uint32_t p0, p1, p2, p3;
                LDSM4(p0, p1, p2, p3, smem_u32(&W2h[nrow * LDB + k0 + acol8]));
                bh0[2 * jj] = p0; bh1[2 * jj] = p2;
                bh0[2 * jj + 1] = p1; bh1[2 * jj + 1] = p3;
                LDSM4(p0, p1, p2, p3, smem_u32(&W2l[nrow * LDB + k0 + acol8]));
                bl0[2 * jj] = p0; bl1[2 * jj] = p2;
                bl0[2 * jj + 1] = p1; bl1[2 * jj + 1] = p3;
            }
            #pragma unroll
            for (int j = 0; j < 4; j++) {
                MMA16816(ac2[j], ah[0], ah[1], ah[2], ah[3], bh0[j], bh1[j]);
                MMA16816(ac2[j], ah[0], ah[1], ah[2], ah[3], bl0[j], bl1[j]);
                MMA16816(ac2[j], al[0], al[1], al[2], al[3], bh0[j], bh1[j]);
            }
        }

        #pragma unroll
        for (int j = 0; j < 4; j++) {
            int col = wn * 32 + j * 8 + cpair;
            int gr1 = row0 + wm * 16 + r_lo, gr2 = gr1 + 8;
            if (gr1 < NN)
                *(float2*)(g_p + (size_t)gr1 * CC + col) = make_float2(ac2[j][0], ac2[j][1]);
            if (gr2 < NN)
                *(float2*)(g_p + (size_t)gr2 * CC + col) = make_float2(ac2[j][2], ac2[j][3]);
        }
    }
}

// ---------------- SpMM width 64 + softmax: one warp per row, MLP-8 batched ----------------
__global__ void k_spmm64_softmax(float* __restrict__ out) {
    int row = (blockIdx.x * blockDim.x + threadIdx.x) >> 5;
    int lane = threadIdx.x & 31;
    if (row >= NN) return;
    int n = min(g_fill[row], CAP);
    const int2* eb = g_edge + (size_t)row * CAP;
    float2 acc0 = make_float2(0.f, 0.f);
    float2 acc1 = make_float2(0.f, 0.f);
    for (int e = 0; e < n; e += 32) {
        int m = min(32, n - e);
        int2 ed = (lane < m) ? eb[e + lane] : make_int2(0, 0);
        int kk = 0;
        for (; kk + 8 <= m; kk += 8) {
            float2 xv[8];
            float  vk[8];
            #pragma unroll
            for (int q = 0; q < 8; q++) {
                int   sk = __shfl_sync(0xffffffffu, ed.x, kk + q);
                vk[q]    = __int_as_float(__shfl_sync(0xffffffffu, ed.y, kk + q));
                xv[q]    = *(const float2*)(g_p + (size_t)sk * CC + lane * 2);
            }
            #pragma unroll
            for (int q = 0; q < 8; q += 2) {
                acc0.x += vk[q] * xv[q].x;     acc0.y += vk[q] * xv[q].y;
                acc1.x += vk[q+1] * xv[q+1].x; acc1.y += vk[q+1] * xv[q+1].y;
            }
        }
        for (; kk < m; kk++) {
            int   sk = __shfl_sync(0xffffffffu, ed.x, kk);
            float vk = __int_as_float(__shfl_sync(0xffffffffu, ed.y, kk));
            float2 xv = *(const float2*)(g_p + (size_t)sk * CC + lane * 2);
            acc0.x += vk * xv.x; acc0.y += vk * xv.y;
        }
    }
    float ax = acc0.x + acc1.x, ay = acc0.y + acc1.y;
    float m2 = fmaxf(ax, ay);
    #pragma unroll
    for (int off = 16; off > 0; off >>= 1)
        m2 = fmaxf(m2, __shfl_xor_sync(0xffffffffu, m2, off));
    float ea = __expf(ax - m2), eb2 = __expf(ay - m2);
    float s = ea + eb2;
    #pragma unroll
    for (int off = 16; off > 0; off >>= 1)
        s += __shfl_xor_sync(0xffffffffu, s, off);
    float inv = 1.f / s;
    *(float2*)(out + (size_t)row * CC + lane * 2) = make_float2(ea * inv, eb2 * inv);
}

// ---------------- launch ----------------
extern "C" void kernel_launch(void* const* d_in, const int* in_sizes, int n_in,
                              void* d_out, int out_size) {
    const float* x    = (const float*)d_in[0];
    const float* vals = (const float*)d_in[1];
    const float* W1   = (const float*)d_in[2];
    const float* W2   = (const float*)d_in[3];
    const int*   src  = (const int*)d_in[4];
    const int*   dst  = (const int*)d_in[5];
    float* out = (float*)d_out;

    const int smemF = (4 * 128 * LDB + 2 * 64 * LDB) * 2;   // 174,080 B
    static bool attr_done = false;
    if (!attr_done) {
        cudaFuncSetAttribute(k_gemm_fused, cudaFuncAttributeMaxDynamicSharedMemorySize, smemF);
        attr_done = true;
    }

    // bucket CSR by dst + weight split
    k_zero<<<(NN + 255) / 256, 256>>>();
    k_scatter<<<(EE + 255) / 256, 256>>>(src, dst, vals);
    k_wsplit<<<(FF * FF + 255) / 256, 256>>>(W1, W2);

    // layer 1 aggregation (1 warp/row, MLP-8, writes bf16 hi/lo)
    k_spmm128<<<(NN * 32 + 255) / 256, 256>>>(x);
    // dense parts of both layers on tensor cores, persistent grid
    k_gemm_fused<<<GGRID, 512, smemF>>>();
    // layer 2 aggregation + softmax (1 warp/row, MLP-8)
    k_spmm64_softmax<<<(NN * 32 + 255) / 256, 256>>>(out);
}

// round 14
// speedup vs baseline: 1.1166x; 1.1001x over previous
#include <cuda_runtime.h>
#include <cuda_bf16.h>
#include <cstdint>

#define NN 50000
#define EE 800000
#define FF 128
#define CC 64
#define CAP 64          // bucket capacity per row (Poisson(16) tail: P(deg>=64) ~ 1e-19)
#define NT ((NN + 127) / 128)   // 391 row tiles
#define GGRID 148

// ---------------- scratch (static device globals; no allocation) ----------------
__device__ int   g_fill[NN];
__device__ int2  g_edge[(size_t)NN * CAP];     // (src, val-bits) bucketed by dst row
__device__ __nv_bfloat16 g_sh[(size_t)NN * FF];  // spmm1 output, hi part
__device__ __nv_bfloat16 g_sl[(size_t)NN * FF];  // spmm1 output, lo part
__device__ __nv_bfloat16 g_w1h[FF * FF], g_w1l[FF * FF];
__device__ __nv_bfloat16 g_w2h[CC * FF], g_w2l[CC * FF];
__device__ float g_p[(size_t)NN * CC];         // relu(s@W1^T)@W2^T pre-aggregation logits

// ---------------- bucket CSR build ----------------
__global__ void k_zero() {
    int i = blockIdx.x * blockDim.x + threadIdx.x;
    if (i < NN) g_fill[i] = 0;
}

// 4 edges per thread, vectorized loads for MLP
__global__ void k_scatter(const int* __restrict__ src, const int* __restrict__ dst,
                          const float* __restrict__ vals) {
    int t = blockIdx.x * blockDim.x + threadIdx.x;
    int e0 = t * 4;
    if (e0 + 3 < EE) {
        int4   s4 = *(const int4*)(src + e0);
        int4   d4 = *(const int4*)(dst + e0);
        float4 v4 = *(const float4*)(vals + e0);
        int ss[4] = {s4.x, s4.y, s4.z, s4.w};
        int dd[4] = {d4.x, d4.y, d4.z, d4.w};
        float vv[4] = {v4.x, v4.y, v4.z, v4.w};
        int pp[4];
        #pragma unroll
        for (int q = 0; q < 4; q++) pp[q] = atomicAdd(&g_fill[dd[q]], 1);
        #pragma unroll
        for (int q = 0; q < 4; q++)
            if (pp[q] < CAP)
                g_edge[(size_t)dd[q] * CAP + pp[q]] = make_int2(ss[q], __float_as_int(vv[q]));
    } else {
        for (int e = e0; e < EE; e++) {
            int d = dst[e];
            int p = atomicAdd(&g_fill[d], 1);
            if (p < CAP)
                g_edge[(size_t)d * CAP + p] = make_int2(src[e], __float_as_int(vals[e]));
        }
    }
}

// ---------------- weight pre-split (once per launch) ----------------
__global__ void k_wsplit(const float* __restrict__ W1, const float* __restrict__ W2) {
    int i = blockIdx.x * blockDim.x + threadIdx.x;
    if (i < FF * FF) {
        float v = W1[i];
        __nv_bfloat16 h = __float2bfloat16(v);
        g_w1h[i] = h;
        g_w1l[i] = __float2bfloat16(v - __bfloat162float(h));
    }
    if (i < CC * FF) {
        float v = W2[i];
        __nv_bfloat16 h = __float2bfloat16(v);
        g_w2h[i] = h;
        g_w2l[i] = __float2bfloat16(v - __bfloat162float(h));
    }
}

// ---------------- SpMM width 128: one warp per row (R9-exact form) ----------------
__global__ void k_spmm128(const float* __restrict__ X) {
    int row = (blockIdx.x * blockDim.x + threadIdx.x) >> 5;
    int lane = threadIdx.x & 31;
    if (row >= NN) return;
    int n = min(g_fill[row], CAP);
    const int2* eb = g_edge + (size_t)row * CAP;
    float4 acc = make_float4(0.f, 0.f, 0.f, 0.f);
    for (int e = 0; e < n; e += 32) {
        int m = min(32, n - e);
        int2 ed = (lane < m) ? eb[e + lane] : make_int2(0, 0);
        #pragma unroll 4
        for (int k = 0; k < m; k++) {
            int   sk = __shfl_sync(0xffffffffu, ed.x, k);
            float vk = __int_as_float(__shfl_sync(0xffffffffu, ed.y, k));
            float4 xv = *(const float4*)(X + (size_t)sk * FF + lane * 4);
            acc.x += vk * xv.x; acc.y += vk * xv.y;
            acc.z += vk * xv.z; acc.w += vk * xv.w;
        }
    }
    size_t base = (size_t)row * FF + lane * 4;
    float v[4] = {acc.x, acc.y, acc.z, acc.w};
    __nv_bfloat16 hh[4], ll[4];
    #pragma unroll
    for (int q = 0; q < 4; q++) {
        hh[q] = __float2bfloat16(v[q]);
        ll[q] = __float2bfloat16(v[q] - __bfloat162float(hh[q]));
    }
    *(uint2*)(g_sh + base) = *(uint2*)hh;
    *(uint2*)(g_sl + base) = *(uint2*)ll;
}

// ---------------- persistent tensor-core fused GEMM ----------------
// p = relu(S @ W1^T) @ W2^T; mma m16n8k16 bf16 hi/lo split (3 MMAs).

#define LDB 136

__device__ __forceinline__ uint32_t smem_u32(const void* p) {
    return (uint32_t)__cvta_generic_to_shared(p);
}

#define LDSM4(r0, r1, r2, r3, addr)                                           \
    asm volatile("ldmatrix.sync.aligned.m8n8.x4.shared.b16 {%0,%1,%2,%3},[%4];" \
                 : "=r"(r0), "=r"(r1), "=r"(r2), "=r"(r3) : "r"(addr))

#define MMA16816(d, a0, a1, a2, a3, b0, b1)                                   \
    asm volatile("mma.sync.aligned.m16n8k16.row.col.f32.bf16.bf16.f32 "        \
                 "{%0,%1,%2,%3},{%4,%5,%6,%7},{%8,%9},{%0,%1,%2,%3};"          \
                 : "+f"(d[0]), "+f"(d[1]), "+f"(d[2]), "+f"(d[3])              \
                 : "r"(a0), "r"(a1), "r"(a2), "r"(a3), "r"(b0), "r"(b1))

__device__ __forceinline__ void split_store(__nv_bfloat16* Hp, __nv_bfloat16* Lp,
                                            int off, float v) {
    __nv_bfloat16 h = __float2bfloat16(v);
    Hp[off] = h;
    Lp[off] = __float2bfloat16(v - __bfloat162float(h));
}

__global__ void __launch_bounds__(512, 1)
k_gemm_fused() {
    extern __shared__ __nv_bfloat16 smb[];
    __nv_bfloat16* Sh  = smb;                     // 128*136
    __nv_bfloat16* Sl  = Sh  + 128 * LDB;
    __nv_bfloat16* W1h = Sl  + 128 * LDB;
    __nv_bfloat16* W1l = W1h + 128 * LDB;
    __nv_bfloat16* W2h = W1l + 128 * LDB;         // 64*136
    __nv_bfloat16* W2l = W2h + 64 * LDB;

    int tid = threadIdx.x;
    int lane = tid & 31, w = tid >> 5;

    for (int idx = tid; idx < 128 * 16; idx += 512) {
        int r = idx >> 4, c8 = idx & 15;
        *(uint4*)(&W1h[r * LDB + c8 * 8]) = ((const uint4*)(g_w1h + r * FF))[c8];
        *(uint4*)(&W1l[r * LDB + c8 * 8]) = ((const uint4*)(g_w1l + r * FF))[c8];
    }
    for (int idx = tid; idx < 64 * 16; idx += 512) {
        int r = idx >> 4, c8 = idx & 15;
        *(uint4*)(&W2h[r * LDB + c8 * 8]) = ((const uint4*)(g_w2h + r * FF))[c8];
        *(uint4*)(&W2l[r * LDB + c8 * 8]) = ((const uint4*)(g_w2l + r * FF))[c8];
    }

    int wm = w & 7;
    int wn = w >> 3;
    int arow = (lane & 15), acol8 = (lane >> 4) << 3;
    int r_lo = lane >> 2, cpair = (lane & 3) * 2;
    const uint4 zero4 = make_uint4(0, 0, 0, 0);

    for (int t = blockIdx.x; t < NT; t += GGRID) {
        int row0 = t * 128;
        __syncthreads();

        for (int idx = tid; idx < 128 * 16; idx += 512) {
            int r = idx >> 4, c8 = idx & 15;
            int gr = row0 + r;
            uint4 vh = zero4, vl = zero4;
            if (gr < NN) {
                vh = ((const uint4*)(g_sh + (size_t)gr * FF))[c8];
                vl = ((const uint4*)(g_sl + (size_t)gr * FF))[c8];
            }
            *(uint4*)(&Sh[r * LDB + c8 * 8]) = vh;
            *(uint4*)(&Sl[r * LDB + c8 * 8]) = vl;
        }
        __syncthreads();

        // ---- phase A: h = relu(S @ W1^T) ----
        float acc[8][4];
        #pragma unroll
        for (int j = 0; j < 8; j++)
            #pragma unroll
            for (int q = 0; q < 4; q++) acc[j][q] = 0.f;

        #pragma unroll
        for (int ks = 0; ks < 8; ks++) {
            int k0 = ks * 16;
            uint32_t ah[4], al[4];
            LDSM4(ah[0], ah[1], ah[2], ah[3],
                  smem_u32(&Sh[(wm * 16 + arow) * LDB + k0 + acol8]));
            LDSM4(al[0], al[1], al[2], al[3],
                  smem_u32(&Sl[(wm * 16 + arow) * LDB + k0 + acol8]));
            uint32_t bh0[8], bh1[8], bl0[8], bl1[8];
            #pragma unroll
            for (int jj = 0; jj < 4; jj++) {
                int nrow = wn * 64 + jj * 16 + arow;
                uint32_t p0, p1, p2, p3;
                LDSM4(p0, p1, p2, p3, smem_u32(&W1h[nrow * LDB + k0 + acol8]));
                bh0[2 * jj] = p0; bh1[2 * jj] = p2;
                bh0[2 * jj + 1] = p1; bh1[2 * jj + 1] = p3;
                LDSM4(p0, p1, p2, p3, smem_u32(&W1l[nrow * LDB + k0 + acol8]));
                bl0[2 * jj] = p0; bl1[2 * jj] = p2;
                bl0[2 * jj + 1] = p1; bl1[2 * jj + 1] = p3;
            }
            #pragma unroll
            for (int j = 0; j < 8; j++) {
                MMA16816(acc[j], ah[0], ah[1], ah[2], ah[3], bh0[j], bh1[j]);
                MMA16816(acc[j], ah[0], ah[1], ah[2], ah[3], bl0[j], bl1[j]);
                MMA16816(acc[j], al[0], al[1], al[2], al[3], bh0[j], bh1[j]);
            }
        }
        __syncthreads();

        #pragma unroll
        for (int j = 0; j < 8; j++) {
            int col = wn * 64 + j * 8 + cpair;
            int r1 = wm * 16 + r_lo, r2 = r1 + 8;
            split_store(Sh, Sl, r1 * LDB + col,     fmaxf(acc[j][0], 0.f));
            split_store(Sh, Sl, r1 * LDB + col + 1, fmaxf(acc[j][1], 0.f));
            split_store(Sh, Sl, r2 * LDB + col,     fmaxf(acc[j][2], 0.f));
            split_store(Sh, Sl, r2 * LDB + col + 1, fmaxf(acc[j][3], 0.f));
        }
        __syncthreads();

        // ---- phase B: p = h @ W2^T ----
        float ac2[4][4];
        #pragma unroll
        for (int j = 0; j < 4; j++)
            #pragma unroll
            for (int q = 0; q < 4; q++) ac2[j][q] = 0.f;

        #pragma unroll
        for (int ks = 0; ks < 8; ks++) {
            int k0 = ks * 16;
            uint32_t ah[4], al[4];
            LDSM4(ah[0], ah[1], ah[2], ah[3],
                  smem_u32(&Sh[(wm * 16 + arow) * LDB + k0 + acol8]));
            LDSM4(al[0], al[1], al[2], al[3],
                  smem_u32(&Sl[(wm * 16 + arow) * LDB + k0 + acol8]));
            uint32_t bh0[4], bh1[4], bl0[4], bl1[4];
            #pragma unroll
            for (int jj = 0; jj < 2; jj++) {
                int nrow = wn * 32 + jj * 16 + arow;
                uint32_t p0, p1, p2, p3;
                LDSM4(p0, p1, p2, p3, smem_u32(&W2h[nrow * LDB + k0 + acol8]));
                bh0[2 * jj] = p0; bh1[2 * jj] = p2;
                bh0[2 * jj + 1] = p1; bh1[2 * jj + 1] = p3;
                LDSM4(p0, p1, p2, p3, smem_u32(&W2l[nrow * LDB + k0 + acol8]));
                bl0[2 * jj] = p0; bl1[2 * jj] = p2;
                bl0[2 * jj + 1] = p1; bl1[2 * jj + 1] = p3;
            }
            #pragma unroll
            for (int j = 0; j < 4; j++) {
                MMA16816(ac2[j], ah[0], ah[1], ah[2], ah[3], bh0[j], bh1[j]);
                MMA16816(ac2[j], ah[0], ah[1], ah[2], ah[3], bl0[j], bl1[j]);
                MMA16816(ac2[j], al[0], al[1], al[2], al[3], bh0[j], bh1[j]);
            }
        }

        #pragma unroll
        for (int j = 0; j < 4; j++) {
            int col = wn * 32 + j * 8 + cpair;
            int gr1 = row0 + wm * 16 + r_lo, gr2 = gr1 + 8;
            if (gr1 < NN)
                *(float2*)(g_p + (size_t)gr1 * CC + col) = make_float2(ac2[j][0], ac2[j][1]);
            if (gr2 < NN)
                *(float2*)(g_p + (size_t)gr2 * CC + col) = make_float2(ac2[j][2], ac2[j][3]);
        }
    }
}

// ---------------- SpMM width 64 + fused softmax: one warp per row (R9-exact) ----------------
__global__ void k_spmm64_softmax(float* __restrict__ out) {
    int row = (blockIdx.x * blockDim.x + threadIdx.x) >> 5;
    int lane = threadIdx.x & 31;
    if (row >= NN) return;
    int n = min(g_fill[row], CAP);
    const int2* eb = g_edge + (size_t)row * CAP;
    float2 acc = make_float2(0.f, 0.f);
    for (int e = 0; e < n; e += 32) {
        int m = min(32, n - e);
        int2 ed = (lane < m) ? eb[e + lane] : make_int2(0, 0);
        #pragma unroll 4
        for (int k = 0; k < m; k++) {
            int   sk = __shfl_sync(0xffffffffu, ed.x, k);
            float vk = __int_as_float(__shfl_sync(0xffffffffu, ed.y, k));
            float2 xv = *(const float2*)(g_p + (size_t)sk * CC + lane * 2);
            acc.x += vk * xv.x; acc.y += vk * xv.y;
        }
    }
    float m2 = fmaxf(acc.x, acc.y);
    #pragma unroll
    for (int off = 16; off > 0; off >>= 1)
        m2 = fmaxf(m2, __shfl_xor_sync(0xffffffffu, m2, off));
    float ea = __expf(acc.x - m2), eb2 = __expf(acc.y - m2);
    float s = ea + eb2;
    #pragma unroll
    for (int off = 16; off > 0; off >>= 1)
        s += __shfl_xor_sync(0xffffffffu, s, off);
    float inv = 1.f / s;
    *(float2*)(out + (size_t)row * CC + lane * 2) = make_float2(ea * inv, eb2 * inv);
}

// ---------------- launch ----------------
extern "C" void kernel_launch(void* const* d_in, const int* in_sizes, int n_in,
                              void* d_out, int out_size) {
    const float* x    = (const float*)d_in[0];
    const float* vals = (const float*)d_in[1];
    const float* W1   = (const float*)d_in[2];
    const float* W2   = (const float*)d_in[3];
    const int*   src  = (const int*)d_in[4];
    const int*   dst  = (const int*)d_in[5];
    float* out = (float*)d_out;

    const int smemF = (4 * 128 * LDB + 2 * 64 * LDB) * 2;   // 174,080 B
    static bool attr_done = false;
    if (!attr_done) {
        cudaFuncSetAttribute(k_gemm_fused, cudaFuncAttributeMaxDynamicSharedMemorySize, smemF);
        attr_done = true;
    }

    // bucket CSR by dst + weight split
    k_zero<<<(NN + 255) / 256, 256>>>();
    k_scatter<<<(EE / 4 + 255) / 256, 256>>>(src, dst, vals);
    k_wsplit<<<(FF * FF + 255) / 256, 256>>>(W1, W2);

    // layer 1 aggregation (1 warp/row, writes bf16 hi/lo)
    k_spmm128<<<(NN * 32 + 255) / 256, 256>>>(x);
    // dense parts of both layers on tensor cores, persistent grid
    k_gemm_fused<<<GGRID, 512, smemF>>>();
    // layer 2 aggregation + softmax (1 warp/row)
    k_spmm64_softmax<<<(NN * 32 + 255) / 256, 256>>>(out);
}